// round 1
// baseline (speedup 1.0000x reference)
#include <cuda_runtime.h>
#include <math.h>

#define TOTAL_V 991
#define BATCH   2048
#define NPARTS  20
#define NEPS    9

__device__ __forceinline__ float ex2f_(float x){ float r; asm("ex2.approx.ftz.f32 %0, %1;" : "=f"(r) : "f"(x)); return r; }
__device__ __forceinline__ float lg2f_(float x){ float r; asm("lg2.approx.ftz.f32 %0, %1;" : "=f"(r) : "f"(x)); return r; }

__constant__ float c_eps[NEPS] = {64.f, 16.f, 4.f, 1.f, 0.25f, 0.0625f, 0.015625f, 0.00390625f, 0.0025f};

__device__ float g_scratch[NPARTS * BATCH];

// One CTA = one (batch, part) Sinkhorn problem. blockDim = ceil32(n).
// SMEM: Cxy,Cxx,Cyy (n*ld each, ld odd -> conflict-free row sweeps) + 20n floats of vectors.
__global__ void sinkhorn_kernel(const float* __restrict__ pred,
                                const float* __restrict__ pc,
                                int n, int ld, int soff, int part, float loga)
{
    extern __shared__ float sm[];
    float* Cxy = sm;
    float* Cxx = Cxy + n * ld;
    float* Cyy = Cxx + n * ld;
    float* xx = Cyy + n * ld;
    float* xy = xx + n;  float* xz = xy + n;
    float* yx = xz + n;  float* yy = yx + n;  float* yz = yy + n;
    float* x2 = yz + n;  float* y2 = x2 + n;
    float* f   = y2 + n;  float* g   = f + n;
    float* px  = g + n;   float* py  = px + n;
    float* fs  = py + n;  float* gs  = fs + n;
    float* pxs = gs + n;  float* pys = pxs + n;
    float* ftv = pys + n; float* gtv = ftv + n;
    float* pxt = gtv + n; float* pyt = pxt + n;

    const int t = threadIdx.x;
    const int b = blockIdx.x;
    const float* X = pred + ((size_t)b * TOTAL_V + soff) * 3;
    const float* Y = pc   + ((size_t)b * TOTAL_V + soff) * 3;

    if (t < n) {
        float ax = X[3*t], ay = X[3*t+1], az = X[3*t+2];
        float bx = Y[3*t], by = Y[3*t+1], bz = Y[3*t+2];
        xx[t] = ax; xy[t] = ay; xz[t] = az;
        yx[t] = bx; yy[t] = by; yz[t] = bz;
        x2[t] = ax*ax + ay*ay + az*az;
        y2[t] = bx*bx + by*by + bz*bz;
        f[t] = 0.f; g[t] = 0.f; px[t] = 0.f; py[t] = 0.f;
    }
    __syncthreads();

    // Build cost matrices: C = 0.5*(|u|^2 + |v|^2) - u.v
    if (t < n) {
        float ax = xx[t], ay = xy[t], az = xz[t];
        float bx = yx[t], by = yy[t], bz = yz[t];
        float ha = 0.5f * x2[t], hb = 0.5f * y2[t];
        float* rxy = Cxy + t * ld;
        float* rxx = Cxx + t * ld;
        float* ryy = Cyy + t * ld;
        #pragma unroll 4
        for (int j = 0; j < n; j++) {
            float ux = xx[j], uy = xy[j], uz = xz[j];
            float vx = yx[j], vy = yy[j], vz = yz[j];
            float hy = 0.5f * y2[j];
            rxy[j] = ha + hy          - (ax*vx + ay*vy + az*vz);
            rxx[j] = ha + 0.5f*x2[j]  - (ax*ux + ay*uy + az*uz);
            ryy[j] = hb + hy          - (bx*vx + by*vy + bz*vz);
        }
    }
    __syncthreads();

    const float LOG2E = 1.44269504088896340736f;
    const float LN2   = 0.69314718055994530942f;

    for (int e = 0; e < NEPS; e++) {
        const float eps = c_eps[e];
        const float k   = LOG2E / eps;   // work in log2 domain: 1 FFMA + 1 EX2 per element
        const float nk  = -k;
        const float c1  = -eps * LN2;    // lse_nat = LN2*(M + log2 S)
        const float c2  = -eps * loga;

        if (t < n) { fs[t] = f[t]*k; gs[t] = g[t]*k; pxs[t] = px[t]*k; pys[t] = py[t]*k; }
        __syncthreads();

        if (t < n) {
            // ft[t]: logsumexp over row t of Cxy against gs
            {
                const float* r = Cxy + t * ld;
                float M = -3.0e38f;
                #pragma unroll 4
                for (int j = 0; j < n; j++) M = fmaxf(M, fmaf(r[j], nk, gs[j]));
                float S = 0.f;
                #pragma unroll 4
                for (int j = 0; j < n; j++) S += ex2f_(fmaf(r[j], nk, gs[j]) - M);
                ftv[t] = fmaf(c1, M + lg2f_(S), c2);
            }
            // gt[t]: logsumexp over column t of Cxy against fs (conflict-free: lanes hit consecutive addrs)
            {
                const float* cp = Cxy + t;
                float M = -3.0e38f;
                #pragma unroll 4
                for (int i = 0; i < n; i++) M = fmaxf(M, fmaf(cp[i*ld], nk, fs[i]));
                float S = 0.f;
                #pragma unroll 4
                for (int i = 0; i < n; i++) S += ex2f_(fmaf(cp[i*ld], nk, fs[i]) - M);
                gtv[t] = fmaf(c1, M + lg2f_(S), c2);
            }
            // px[t] update: rows of Cxx
            {
                const float* r = Cxx + t * ld;
                float M = -3.0e38f;
                #pragma unroll 4
                for (int j = 0; j < n; j++) M = fmaxf(M, fmaf(r[j], nk, pxs[j]));
                float S = 0.f;
                #pragma unroll 4
                for (int j = 0; j < n; j++) S += ex2f_(fmaf(r[j], nk, pxs[j]) - M);
                pxt[t] = 0.5f * (px[t] + fmaf(c1, M + lg2f_(S), c2));
            }
            // py[t] update: rows of Cyy
            {
                const float* r = Cyy + t * ld;
                float M = -3.0e38f;
                #pragma unroll 4
                for (int j = 0; j < n; j++) M = fmaxf(M, fmaf(r[j], nk, pys[j]));
                float S = 0.f;
                #pragma unroll 4
                for (int j = 0; j < n; j++) S += ex2f_(fmaf(r[j], nk, pys[j]) - M);
                pyt[t] = 0.5f * (py[t] + fmaf(c1, M + lg2f_(S), c2));
            }
        }
        __syncthreads();
        if (t < n) {
            f[t]  = 0.5f * (f[t] + ftv[t]);
            g[t]  = 0.5f * (g[t] + gtv[t]);
            px[t] = pxt[t];
            py[t] = pyt[t];
        }
        __syncthreads();
    }

    // div = mean(f - px) + mean(g - py) = sum(f-px+g-py)/n
    float val = (t < n) ? (f[t] - px[t] + g[t] - py[t]) : 0.f;
    #pragma unroll
    for (int o = 16; o; o >>= 1) val += __shfl_xor_sync(0xffffffffu, val, o);
    if ((t & 31) == 0) ftv[t >> 5] = val;   // ftv is dead here; n >= 28 >= nwarps
    __syncthreads();
    if (t == 0) {
        float s = 0.f;
        const int nw = (blockDim.x + 31) >> 5;
        for (int w = 0; w < nw; w++) s += ftv[w];
        g_scratch[part * BATCH + b] = s / (float)n;
    }
}

// Deterministic final reduction: sum(all divs) / BATCH
__global__ void reduce_kernel(float* __restrict__ out)
{
    __shared__ float red[32];
    float s = 0.f;
    for (int i = threadIdx.x; i < NPARTS * BATCH; i += 1024) s += g_scratch[i];
    #pragma unroll
    for (int o = 16; o; o >>= 1) s += __shfl_xor_sync(0xffffffffu, s, o);
    if ((threadIdx.x & 31) == 0) red[threadIdx.x >> 5] = s;
    __syncthreads();
    if (threadIdx.x < 32) {
        float v = red[threadIdx.x];
        #pragma unroll
        for (int o = 16; o; o >>= 1) v += __shfl_xor_sync(0xffffffffu, v, o);
        if (threadIdx.x == 0) out[0] = v * (1.0f / (float)BATCH);
    }
}

extern "C" void kernel_launch(void* const* d_in, const int* in_sizes, int n_in,
                              void* d_out, int out_size)
{
    const float* pred = (const float*)d_in[0];
    const float* pc   = (const float*)d_in[1];

    static const int VN[NPARTS] = {45,61,43,45,92,34,41,62,44,44,58,42,40,60,41,35,64,28,50,62};

    // Max dynamic smem: n=92, ld=93: (3*92*93 + 20*92)*4 = 110032 bytes
    cudaFuncSetAttribute(sinkhorn_kernel, cudaFuncAttributeMaxDynamicSharedMemorySize, 110032);

    int off = 0;
    for (int p = 0; p < NPARTS; p++) {
        const int n  = VN[p];
        const int ld = (n & 1) ? n : n + 1;          // odd stride -> conflict-free row sweeps
        const int threads = ((n + 31) / 32) * 32;
        const size_t smem = (size_t)(3 * n * ld + 20 * n) * sizeof(float);
        const float loga = -logf((float)n);
        sinkhorn_kernel<<<BATCH, threads, smem>>>(pred, pc, n, ld, off, p, loga);
        off += n;
    }
    reduce_kernel<<<1, 1024>>>((float*)d_out);
}

// round 2
// speedup vs baseline: 1.1565x; 1.1565x over previous
#include <cuda_runtime.h>
#include <math.h>

#define TOTAL_V 991
#define BATCH   2048
#define NPARTS  20
#define NEPS    9

__device__ __forceinline__ float ex2f_(float x){ float r; asm("ex2.approx.ftz.f32 %0, %1;" : "=f"(r) : "f"(x)); return r; }
__device__ __forceinline__ float lg2f_(float x){ float r; asm("lg2.approx.ftz.f32 %0, %1;" : "=f"(r) : "f"(x)); return r; }

__constant__ float c_eps[NEPS] = {64.f, 16.f, 4.f, 1.f, 0.25f, 0.0625f, 0.015625f, 0.00390625f, 0.0025f};

// Parts reordered into size classes: A (n<=45, 12 parts), B (46..64, 7 parts), C (92, 1 part).
// {n, ld, soff, 0}; ld = multiple of 4 with (ld/4) odd -> conflict-free float4 row loads.
__constant__ int4 c_desc[NPARTS] = {
    {45,52,  0,0},{43,44,106,0},{45,52,149,0},{34,36,286,0},{41,44,320,0},{44,44,423,0},
    {44,44,467,0},{42,44,569,0},{40,44,611,0},{41,44,711,0},{35,36,752,0},{28,28,851,0},
    {61,68, 45,0},{62,68,361,0},{58,60,511,0},{60,60,651,0},{64,68,787,0},{50,52,879,0},{62,68,929,0},
    {92,92,194,0}
};

__device__ float g_scratch[NPARTS * BATCH];

// Vectorized two-pass logsumexp over one padded row. Pads: C=+1e30, vec=-1e30 ->
// v_pad ~ -1e30..-6e32 (finite), loses every fmax, ex2 underflows to 0 (FTZ). Safe.
__device__ __forceinline__ float lse_row(const float* __restrict__ rowp,
                                         const float* __restrict__ vp,
                                         int nc4, float nk, float c1, float c2)
{
    const float4* r = (const float4*)rowp;
    const float4* v = (const float4*)vp;
    float M0 = -3.0e38f, M1 = -3.0e38f;
    #pragma unroll 2
    for (int c = 0; c < nc4; c++) {
        float4 a = r[c]; float4 w = v[c];
        M0 = fmaxf(M0, fmaxf(fmaf(a.x, nk, w.x), fmaf(a.y, nk, w.y)));
        M1 = fmaxf(M1, fmaxf(fmaf(a.z, nk, w.z), fmaf(a.w, nk, w.w)));
    }
    const float M = fmaxf(M0, M1);
    float S0 = 0.f, S1 = 0.f;
    #pragma unroll 2
    for (int c = 0; c < nc4; c++) {
        float4 a = r[c]; float4 w = v[c];
        S0 += ex2f_(fmaf(a.x, nk, w.x) - M) + ex2f_(fmaf(a.z, nk, w.z) - M);
        S1 += ex2f_(fmaf(a.y, nk, w.y) - M) + ex2f_(fmaf(a.w, nk, w.w) - M);
    }
    return fmaf(c1, M + lg2f_(S0 + S1), c2);
}

// TP=true: 4 matrices (Cxy, Cxx, Cyy, Cyx=Cxy^T), all 4 sweeps vectorized row sweeps.
// TP=false (n=92): 3 matrices; gt uses the scalar conflict-free column sweep.
template<bool TP>
__global__ void sinkhorn_kernel(const float* __restrict__ pred,
                                const float* __restrict__ pc, int first)
{
    const int pl = blockIdx.x >> 11;          // part within class
    const int4 d = c_desc[first + pl];
    const int n = d.x, ld = d.y, soff = d.z;
    const int b = blockIdx.x & 2047;

    extern __shared__ float sm[];
    const int msz = n * ld;
    float* Cxy = sm;
    float* Cxx = Cxy + msz;
    float* Cyy = Cxx + msz;
    float* Cyx = Cyy + msz;                   // only if TP
    float* V   = sm + (TP ? 4 : 3) * msz;
    float* gs  = V;            float* fs  = V + ld;
    float* pxs = V + 2 * ld;   float* pys = V + 3 * ld;
    float* xx  = V + 4 * ld;   float* xy  = V + 5 * ld;   float* xz = V + 6 * ld;
    float* yx  = V + 7 * ld;   float* yy  = V + 8 * ld;   float* yz = V + 9 * ld;
    float* x2  = V + 10 * ld;  float* y2  = V + 11 * ld;

    const int t = threadIdx.x;
    const float* X = pred + ((size_t)b * TOTAL_V + soff) * 3;
    const float* Y = pc   + ((size_t)b * TOTAL_V + soff) * 3;

    if (t < n) {
        float ax = X[3*t], ay = X[3*t+1], az = X[3*t+2];
        float bx = Y[3*t], by = Y[3*t+1], bz = Y[3*t+2];
        xx[t] = ax; xy[t] = ay; xz[t] = az;
        yx[t] = bx; yy[t] = by; yz[t] = bz;
        x2[t] = ax*ax + ay*ay + az*az;
        y2[t] = bx*bx + by*by + bz*bz;
    }
    // pad slots of the scaled-vector arrays (never rewritten afterwards)
    for (int j = n + t; j < ld; j += blockDim.x) {
        gs[j] = -1e30f; fs[j] = -1e30f; pxs[j] = -1e30f; pys[j] = -1e30f;
    }
    __syncthreads();

    if (t < n) {
        const float ax = xx[t], ay = xy[t], az = xz[t];
        const float bx = yx[t], by = yy[t], bz = yz[t];
        const float ha = 0.5f * x2[t], hb = 0.5f * y2[t];
        float* rxy = Cxy + t * ld;
        float* rxx = Cxx + t * ld;
        float* ryy = Cyy + t * ld;
        float* ryx = Cyx + t * ld;
        #pragma unroll 4
        for (int j = 0; j < n; j++) {
            float ux = xx[j], uy = xy[j], uz = xz[j];
            float vx = yx[j], vy = yy[j], vz = yz[j];
            float hx2 = 0.5f * x2[j], hy2 = 0.5f * y2[j];
            rxy[j] = ha + hy2 - (ax*vx + ay*vy + az*vz);
            rxx[j] = ha + hx2 - (ax*ux + ay*uy + az*uz);
            ryy[j] = hb + hy2 - (bx*vx + by*vy + bz*vz);
            if (TP) ryx[j] = hb + hx2 - (bx*ux + by*uy + bz*uz);
        }
        for (int j = n; j < ld; j++) {
            rxy[j] = 1e30f; rxx[j] = 1e30f; ryy[j] = 1e30f;
            if (TP) ryx[j] = 1e30f;
        }
    }

    const float LOG2E = 1.44269504088896340736f;
    const float LN2   = 0.69314718055994530942f;
    const float l2n   = lg2f_((float)n);       // logb = loga = -ln(n) = -LN2*l2n
    const int   nc4   = ld >> 2;

    float myf = 0.f, myg = 0.f, mypx = 0.f, mypy = 0.f;

    for (int e = 0; e < NEPS; e++) {
        const float eps = c_eps[e];
        const float k   = LOG2E / eps;
        const float nk  = -k;
        const float c1  = -eps * LN2;
        const float c2  = eps * LN2 * l2n;     // -eps*logb

        if (t < n) { gs[t] = myg*k; fs[t] = myf*k; pxs[t] = mypx*k; pys[t] = mypy*k; }
        __syncthreads();

        if (t < n) {
            const float ft  = lse_row(Cxy + t*ld, gs,  nc4, nk, c1, c2);
            float gt;
            if (TP) {
                gt = lse_row(Cyx + t*ld, fs, nc4, nk, c1, c2);
            } else {
                // column t of Cxy: lanes hit consecutive addresses -> conflict-free
                const float* cp = Cxy + t;
                float M = -3.0e38f;
                #pragma unroll 4
                for (int i = 0; i < n; i++) M = fmaxf(M, fmaf(cp[i*ld], nk, fs[i]));
                float S0 = 0.f, S1 = 0.f;
                #pragma unroll 4
                for (int i = 0; i < n; i++) {
                    float v = fmaf(cp[i*ld], nk, fs[i]) - M;
                    if (i & 1) S1 += ex2f_(v); else S0 += ex2f_(v);
                }
                gt = fmaf(c1, M + lg2f_(S0 + S1), c2);
            }
            const float pxn = lse_row(Cxx + t*ld, pxs, nc4, nk, c1, c2);
            const float pyn = lse_row(Cyy + t*ld, pys, nc4, nk, c1, c2);
            myf  = 0.5f * (myf  + ft);
            myg  = 0.5f * (myg  + gt);
            mypx = 0.5f * (mypx + pxn);
            mypy = 0.5f * (mypy + pyn);
        }
        __syncthreads();
    }

    // div = sum(f - px + g - py)/n ; deterministic CTA reduction (reuse gs, all sweeps done)
    float val = (t < n) ? (myf - mypx + myg - mypy) : 0.f;
    #pragma unroll
    for (int o = 16; o; o >>= 1) val += __shfl_xor_sync(0xffffffffu, val, o);
    if ((t & 31) == 0) gs[t >> 5] = val;
    __syncthreads();
    if (t == 0) {
        float s = 0.f;
        const int nw = (blockDim.x + 31) >> 5;
        for (int w = 0; w < nw; w++) s += gs[w];
        g_scratch[(first + pl) * BATCH + b] = s / (float)n;
    }
}

__global__ void reduce_kernel(float* __restrict__ out)
{
    __shared__ float red[32];
    float s = 0.f;
    for (int i = threadIdx.x; i < NPARTS * BATCH; i += 1024) s += g_scratch[i];
    #pragma unroll
    for (int o = 16; o; o >>= 1) s += __shfl_xor_sync(0xffffffffu, s, o);
    if ((threadIdx.x & 31) == 0) red[threadIdx.x >> 5] = s;
    __syncthreads();
    if (threadIdx.x < 32) {
        float v = red[threadIdx.x];
        #pragma unroll
        for (int o = 16; o; o >>= 1) v += __shfl_xor_sync(0xffffffffu, v, o);
        if (threadIdx.x == 0) out[0] = v * (1.0f / (float)BATCH);
    }
}

extern "C" void kernel_launch(void* const* d_in, const int* in_sizes, int n_in,
                              void* d_out, int out_size)
{
    const float* pred = (const float*)d_in[0];
    const float* pc   = (const float*)d_in[1];

    // SMEM: (4n+12)*ld*4 for TP; (3n+12)*ld*4 for n=92
    const int smemA = (4*45 + 12) * 52 * 4;   // 39,936
    const int smemB = (4*64 + 12) * 68 * 4;   // 72,896
    const int smemC = (3*92 + 12) * 92 * 4;   // 105,984

    cudaFuncSetAttribute(sinkhorn_kernel<true>,  cudaFuncAttributeMaxDynamicSharedMemorySize, smemB);
    cudaFuncSetAttribute(sinkhorn_kernel<false>, cudaFuncAttributeMaxDynamicSharedMemorySize, smemC);

    sinkhorn_kernel<true ><<<12 * BATCH, 64, smemA>>>(pred, pc, 0);   // class A: n<=45
    sinkhorn_kernel<true ><<< 7 * BATCH, 64, smemB>>>(pred, pc, 12);  // class B: 46..64
    sinkhorn_kernel<false><<< 1 * BATCH, 96, smemC>>>(pred, pc, 19);  // class C: n=92
    reduce_kernel<<<1, 1024>>>((float*)d_out);
}

// round 3
// speedup vs baseline: 1.9184x; 1.6587x over previous
#include <cuda_runtime.h>
#include <math.h>

#define TOTAL_V 991
#define BATCH   2048
#define NPARTS  20
#define NEPS    9

__device__ __forceinline__ float ex2f_(float x){ float r; asm("ex2.approx.ftz.f32 %0, %1;" : "=f"(r) : "f"(x)); return r; }
__device__ __forceinline__ float lg2f_(float x){ float r; asm("lg2.approx.ftz.f32 %0, %1;" : "=f"(r) : "f"(x)); return r; }

__constant__ float c_eps[NEPS] = {64.f, 16.f, 4.f, 1.f, 0.25f, 0.0625f, 0.015625f, 0.00390625f, 0.0025f};

// Size classes: A (n<=45, 12 parts), B (46..64, 7 parts), C (92, 1 part).
// {n, ld, soff, 0}; ld multiple of 4 with (ld/4) odd -> conflict-free float4 row loads.
__constant__ int4 c_desc[NPARTS] = {
    {45,52,  0,0},{43,44,106,0},{45,52,149,0},{34,36,286,0},{41,44,320,0},{44,44,423,0},
    {44,44,467,0},{42,44,569,0},{40,44,611,0},{41,44,711,0},{35,36,752,0},{28,28,851,0},
    {61,68, 45,0},{62,68,361,0},{58,60,511,0},{60,60,651,0},{64,68,787,0},{50,52,879,0},{62,68,929,0},
    {92,92,194,0}
};

__device__ float g_scratch[NPARTS * BATCH];

// Vectorized two-pass logsumexp over one padded row.
// Pads: C=+1e30, vec=-1e30 -> finite huge-negative, loses fmax, ex2 underflows (FTZ). Safe.
__device__ __forceinline__ float lse_row(const float* __restrict__ rowp,
                                         const float* __restrict__ vp,
                                         int nc4, float nk, float c1, float c2)
{
    const float4* r = (const float4*)rowp;
    const float4* v = (const float4*)vp;
    float M0 = -3.0e38f, M1 = -3.0e38f;
    #pragma unroll 2
    for (int c = 0; c < nc4; c++) {
        float4 a = r[c]; float4 w = v[c];
        M0 = fmaxf(M0, fmaxf(fmaf(a.x, nk, w.x), fmaf(a.y, nk, w.y)));
        M1 = fmaxf(M1, fmaxf(fmaf(a.z, nk, w.z), fmaf(a.w, nk, w.w)));
    }
    const float M = fmaxf(M0, M1);
    float S0 = 0.f, S1 = 0.f;
    #pragma unroll 2
    for (int c = 0; c < nc4; c++) {
        float4 a = r[c]; float4 w = v[c];
        S0 += ex2f_(fmaf(a.x, nk, w.x) - M) + ex2f_(fmaf(a.z, nk, w.z) - M);
        S1 += ex2f_(fmaf(a.y, nk, w.y) - M) + ex2f_(fmaf(a.w, nk, w.w) - M);
    }
    return fmaf(c1, M + lg2f_(S0 + S1), c2);
}

__device__ __forceinline__ void build_row(float* __restrict__ row,
                                          float lx, float ly, float lz, float hl2,
                                          const float* __restrict__ ax, const float* __restrict__ ay,
                                          const float* __restrict__ az, const float* __restrict__ a2,
                                          int n, int ld)
{
    #pragma unroll 4
    for (int j = 0; j < n; j++)
        row[j] = hl2 + 0.5f * a2[j] - (lx*ax[j] + ly*ay[j] + lz*az[j]);
    for (int j = n; j < ld; j++) row[j] = 1e30f;
}

// Thread (g, r): g in 0..3 = sweep group (f, g, px, py), r = row.
// TP=true: 4 matrices Cxy,Cyx,Cxx,Cyy -> all groups run identical vectorized row sweeps
//          (divergence-free even with non-warp-aligned group boundaries).
// TP=false (n=92): 3 matrices; group 1 does the scalar conflict-free column sweep of Cxy
//          (RS=96 keeps groups warp-aligned).
template<int RS, bool TP>
__global__ void sinkhorn_kernel(const float* __restrict__ pred,
                                const float* __restrict__ pc, int first)
{
    const int pl = blockIdx.x >> 11;
    const int4 d = c_desc[first + pl];
    const int n = d.x, ld = d.y, soff = d.z;
    const int b = blockIdx.x & 2047;

    extern __shared__ float sm[];
    const int msz = n * ld;
    float* V   = sm + (TP ? 4 : 3) * msz;
    float* fs  = V;           float* gs  = V + ld;
    float* pxs = V + 2 * ld;  float* pys = V + 3 * ld;
    float* xx  = V + 4 * ld;  float* xy  = V + 5 * ld;  float* xz = V + 6 * ld;
    float* yx  = V + 7 * ld;  float* yy  = V + 8 * ld;  float* yz = V + 9 * ld;
    float* x2  = V + 10 * ld; float* y2  = V + 11 * ld;

    const int t = threadIdx.x;
    const int g = t / RS;          // RS is a compile-time constant
    const int r = t - g * RS;
    const bool act = (g < 4) && (r < n);

    if (g == 0 && r < n) {
        const float* X = pred + ((size_t)b * TOTAL_V + soff + r) * 3;
        float ax = X[0], ay = X[1], az = X[2];
        xx[r] = ax; xy[r] = ay; xz[r] = az;
        x2[r] = ax*ax + ay*ay + az*az;
    }
    if (g == 1 && r < n) {
        const float* Y = pc + ((size_t)b * TOTAL_V + soff + r) * 3;
        float bx = Y[0], by = Y[1], bz = Y[2];
        yx[r] = bx; yy[r] = by; yz[r] = bz;
        y2[r] = bx*bx + by*by + bz*bz;
    }
    for (int j = n + t; j < ld; j += blockDim.x) {
        fs[j] = -1e30f; gs[j] = -1e30f; pxs[j] = -1e30f; pys[j] = -1e30f;
    }
    __syncthreads();

    // Build: group g builds row r of its matrix.
    if (act) {
        if (TP) {
            // g0:Cxy(X,Y)  g1:Cyx(Y,X)  g2:Cxx(X,X)  g3:Cyy(Y,Y)
            const bool lX = (g == 0) || (g == 2);
            const bool rX = (g == 1) || (g == 2);
            const float lx = lX ? xx[r] : yx[r];
            const float ly = lX ? xy[r] : yy[r];
            const float lz = lX ? xz[r] : yz[r];
            const float hl2 = 0.5f * (lX ? x2[r] : y2[r]);
            build_row(sm + g*msz + r*ld, lx, ly, lz, hl2,
                      rX ? xx : yx, rX ? xy : yy, rX ? xz : yz, rX ? x2 : y2, n, ld);
        } else {
            // matrices: 0:Cxy  1:Cxx  2:Cyy ; group 1 builds nothing
            if (g != 1) {
                const int m = (g == 0) ? 0 : (g == 2) ? 1 : 2;
                const bool lX = (g == 0) || (g == 2);
                const bool rX = (g == 2);
                const float lx = lX ? xx[r] : yx[r];
                const float ly = lX ? xy[r] : yy[r];
                const float lz = lX ? xz[r] : yz[r];
                const float hl2 = 0.5f * (lX ? x2[r] : y2[r]);
                build_row(sm + m*msz + r*ld, lx, ly, lz, hl2,
                          rX ? xx : yx, rX ? xy : yy, rX ? xz : yz, rX ? x2 : y2, n, ld);
            }
        }
    }

    const float LOG2E = 1.44269504088896340736f;
    const float LN2   = 0.69314718055994530942f;
    const float l2n   = lg2f_((float)n);
    const int   nc4   = ld >> 2;

    // per-thread pointers
    float* wv = V + g * ld;                                   // scaled vec this group writes
    const float* rv = V + ((g < 2) ? (1 - g) : g) * ld;        // scaled vec this group reads
    const float* Cm = TP ? (sm + g * msz)
                         : (sm + ((g < 2) ? 0 : (g - 1)) * msz);

    float myv = 0.f;

    for (int e = 0; e < NEPS; e++) {
        const float eps = c_eps[e];
        const float k   = LOG2E / eps;
        const float nk  = -k;
        const float c1  = -eps * LN2;
        const float c2  = eps * LN2 * l2n;   // -eps*logb (loga == logb == -ln n)

        if (act) wv[r] = myv * k;
        __syncthreads();   // also orders matrix build before first sweep

        if (act) {
            float lse;
            if (!TP && g == 1) {
                // column r of Cxy against fs: lanes hit consecutive addrs -> conflict-free
                const float* cp = Cm + r;
                float M = -3.0e38f;
                #pragma unroll 4
                for (int i = 0; i < n; i++) M = fmaxf(M, fmaf(cp[i*ld], nk, fs[i]));
                float S0 = 0.f, S1 = 0.f;
                #pragma unroll 4
                for (int i = 0; i < n; i++) {
                    float v = fmaf(cp[i*ld], nk, fs[i]) - M;
                    if (i & 1) S1 += ex2f_(v); else S0 += ex2f_(v);
                }
                lse = fmaf(c1, M + lg2f_(S0 + S1), c2);
            } else {
                lse = lse_row(Cm + r*ld, rv, nc4, nk, c1, c2);
            }
            myv = 0.5f * (myv + lse);
        }
        __syncthreads();   // WAR: sweeps done before next scaled write
    }

    // div = (sum_f + sum_g - sum_px - sum_py)/n
    float val = act ? ((g < 2) ? myv : -myv) : 0.f;
    #pragma unroll
    for (int o = 16; o; o >>= 1) val += __shfl_xor_sync(0xffffffffu, val, o);
    if ((t & 31) == 0) fs[t >> 5] = val;   // fs dead; nwarps <= 12 <= ld
    __syncthreads();
    if (t == 0) {
        float s = 0.f;
        const int nw = (blockDim.x + 31) >> 5;
        for (int w = 0; w < nw; w++) s += fs[w];
        g_scratch[(first + pl) * BATCH + b] = s / (float)n;
    }
}

__global__ void reduce_kernel(float* __restrict__ out)
{
    __shared__ float red[32];
    float s = 0.f;
    for (int i = threadIdx.x; i < NPARTS * BATCH; i += 1024) s += g_scratch[i];
    #pragma unroll
    for (int o = 16; o; o >>= 1) s += __shfl_xor_sync(0xffffffffu, s, o);
    if ((threadIdx.x & 31) == 0) red[threadIdx.x >> 5] = s;
    __syncthreads();
    if (threadIdx.x < 32) {
        float v = red[threadIdx.x];
        #pragma unroll
        for (int o = 16; o; o >>= 1) v += __shfl_xor_sync(0xffffffffu, v, o);
        if (threadIdx.x == 0) out[0] = v * (1.0f / (float)BATCH);
    }
}

extern "C" void kernel_launch(void* const* d_in, const int* in_sizes, int n_in,
                              void* d_out, int out_size)
{
    const float* pred = (const float*)d_in[0];
    const float* pc   = (const float*)d_in[1];

    // SMEM: A: (4*45+12)*52*4 = 39,936 -> 5 CTAs/SM (28 warps)
    //       B: (4*64+12)*68*4 = 72,896 -> 3 CTAs/SM (24 warps)
    //       C: (3*92+12)*92*4 = 105,984 -> 2 CTAs/SM (24 warps)
    const int smemA = (4*45 + 12) * 52 * 4;
    const int smemB = (4*64 + 12) * 68 * 4;
    const int smemC = (3*92 + 12) * 92 * 4;

    cudaFuncSetAttribute(sinkhorn_kernel<45,true >, cudaFuncAttributeMaxDynamicSharedMemorySize, smemA);
    cudaFuncSetAttribute(sinkhorn_kernel<64,true >, cudaFuncAttributeMaxDynamicSharedMemorySize, smemB);
    cudaFuncSetAttribute(sinkhorn_kernel<96,false>, cudaFuncAttributeMaxDynamicSharedMemorySize, smemC);

    sinkhorn_kernel<45,true ><<<12 * BATCH, 192, smemA>>>(pred, pc, 0);   // 4*45=180 -> 192
    sinkhorn_kernel<64,true ><<< 7 * BATCH, 256, smemB>>>(pred, pc, 12);
    sinkhorn_kernel<96,false><<< 1 * BATCH, 384, smemC>>>(pred, pc, 19);
    reduce_kernel<<<1, 1024>>>((float*)d_out);
}

// round 4
// speedup vs baseline: 2.4833x; 1.2944x over previous
#include <cuda_runtime.h>
#include <math.h>

#define TOTAL_V 991
#define BATCH   2048
#define NPARTS  20
#define NEPS    9

__device__ __forceinline__ float ex2f_(float x){ float r; asm("ex2.approx.ftz.f32 %0, %1;" : "=f"(r) : "f"(x)); return r; }
__device__ __forceinline__ float lg2f_(float x){ float r; asm("lg2.approx.ftz.f32 %0, %1;" : "=f"(r) : "f"(x)); return r; }

__constant__ float c_eps[NEPS] = {64.f, 16.f, 4.f, 1.f, 0.25f, 0.0625f, 0.015625f, 0.00390625f, 0.0025f};

// Parts grouped into 5 compile-time classes (by register row length NC4R = ld/4 max):
// K1: idx 0..8   n=45,43,45,41,44,44,42,40,41  (ld 52/44)  NC4R=13
// K2: idx 9..11  n=34,35,28                    (ld 36/28)  NC4R=9
// K3: idx 12..15 n=61,62,64,62                 (ld 68)     NC4R=17
// K4: idx 16..18 n=58,60,50                    (ld 60/52)  NC4R=15
// K5: idx 19     n=92                          (ld 92)     NC4R=23
// {n, ld, soff, 0}; ld multiple of 4, (ld/4) odd -> conflict-free float4 row loads.
__constant__ int4 c_desc[NPARTS] = {
    {45,52,  0,0},{43,44,106,0},{45,52,149,0},{41,44,320,0},{44,44,423,0},
    {44,44,467,0},{42,44,569,0},{40,44,611,0},{41,44,711,0},
    {34,36,286,0},{35,36,752,0},{28,28,851,0},
    {61,68, 45,0},{62,68,361,0},{64,68,787,0},{62,68,929,0},
    {58,60,511,0},{60,60,651,0},{50,52,879,0},
    {92,92,194,0}
};

__device__ float g_scratch[NPARTS * BATCH];

// Thread (g, r): g in 0..3 = sweep (f, g, px, py), r = row. 4 matrices Cxy,Cyx,Cxx,Cyy.
// Fused two-pass logsumexp: z = nk*C + vec held in registers; pass2 reads no shared.
// Scaled vectors double-buffered -> ONE barrier per eps level.
// Pads: C=+1e30, vec=-1e30 -> z_pad huge-negative finite; loses fmax, ex2 FTZ-underflows to 0.
template<int RS, int NC4R, int THREADS, int MINCTAS>
__global__ void __launch_bounds__(THREADS, MINCTAS)
sinkhorn_kernel(const float* __restrict__ pred, const float* __restrict__ pc, int first)
{
    const int pl = blockIdx.x >> 11;
    const int4 d = c_desc[first + pl];
    const int n = d.x, ld = d.y, soff = d.z;
    const int b = blockIdx.x & 2047;
    const int nc4 = ld >> 2;

    extern __shared__ float sm[];
    const int msz = n * ld;
    float* V  = sm + 4 * msz;          // 8 scaled (double-buffered) + 8 geometry arrays
    float* xx = V + 8*ld;  float* xy = V + 9*ld;   float* xz = V + 10*ld;
    float* yx = V + 11*ld; float* yy = V + 12*ld;  float* yz = V + 13*ld;
    float* x2 = V + 14*ld; float* y2 = V + 15*ld;

    const int t = threadIdx.x;
    const int g = t / RS;
    const int r = t - g * RS;
    const bool act = (g < 4) && (r < n);

    if (g == 0 && r < n) {
        const float* X = pred + ((size_t)b * TOTAL_V + soff + r) * 3;
        float ax = X[0], ay = X[1], az = X[2];
        xx[r] = ax; xy[r] = ay; xz[r] = az;
        x2[r] = ax*ax + ay*ay + az*az;
    }
    if (g == 1 && r < n) {
        const float* Y = pc + ((size_t)b * TOTAL_V + soff + r) * 3;
        float bx = Y[0], by = Y[1], bz = Y[2];
        yx[r] = bx; yy[r] = by; yz[r] = bz;
        y2[r] = bx*bx + by*by + bz*bz;
    }
    // pad all 8 scaled arrays (both buffers)
    for (int j = n + t; j < ld; j += THREADS) {
        #pragma unroll
        for (int a = 0; a < 8; a++) V[a*ld + j] = -1e30f;
    }
    __syncthreads();

    // Build: group g builds row r of its matrix. g0:Cxy(X,Y) g1:Cyx(Y,X) g2:Cxx g3:Cyy
    if (act) {
        const bool lX = (g == 0) || (g == 2);
        const bool rX = (g == 1) || (g == 2);
        const float lx = lX ? xx[r] : yx[r];
        const float ly = lX ? xy[r] : yy[r];
        const float lz = lX ? xz[r] : yz[r];
        const float hl2 = 0.5f * (lX ? x2[r] : y2[r]);
        const float4* ax4 = (const float4*)(rX ? xx : yx);
        const float4* ay4 = (const float4*)(rX ? xy : yy);
        const float4* az4 = (const float4*)(rX ? xz : yz);
        const float4* a24 = (const float4*)(rX ? x2 : y2);
        float4* row4 = (float4*)(sm + g*msz + r*ld);
        #pragma unroll
        for (int c = 0; c < NC4R; c++) if (c < nc4) {
            float4 ax = ax4[c], ay = ay4[c], az = az4[c], a2 = a24[c];
            float4 o;
            o.x = fmaf(-lx, ax.x, fmaf(-ly, ay.x, fmaf(-lz, az.x, fmaf(0.5f, a2.x, hl2))));
            o.y = fmaf(-lx, ax.y, fmaf(-ly, ay.y, fmaf(-lz, az.y, fmaf(0.5f, a2.y, hl2))));
            o.z = fmaf(-lx, ax.z, fmaf(-ly, ay.z, fmaf(-lz, az.z, fmaf(0.5f, a2.z, hl2))));
            o.w = fmaf(-lx, ax.w, fmaf(-ly, ay.w, fmaf(-lz, az.w, fmaf(0.5f, a2.w, hl2))));
            row4[c] = o;
        }
        float* row = sm + g*msz + r*ld;
        for (int j = n; j < ld; j++) row[j] = 1e30f;   // overwrite tail garbage
    }

    const float LOG2E = 1.44269504088896340736f;
    const float LN2   = 0.69314718055994530942f;
    const float l2n   = lg2f_((float)n);
    const int rg = (g < 2) ? (1 - g) : g;             // vec each group reads
    const float4* rr = (const float4*)(sm + g*msz + r*ld);

    float myv = 0.f;

    for (int e = 0; e < NEPS; e++) {
        const float eps = c_eps[e];
        const float k   = LOG2E / eps;
        const float nk  = -k;
        const float c1  = -eps * LN2;
        const float c2  = eps * LN2 * l2n;            // -eps*logb (loga == logb)

        float* wv = V + ((e & 1) * 4 + g) * ld;
        if (act) wv[r] = myv * k;
        __syncthreads();   // single barrier per eps (double-buffered vecs)

        if (act) {
            const float4* vv = (const float4*)(V + ((e & 1) * 4 + rg) * ld);
            float4 z[NC4R];
            float M0 = -3.0e38f, M1 = -3.0e38f;
            #pragma unroll
            for (int c = 0; c < NC4R; c++) if (c < nc4) {
                float4 a = rr[c]; float4 w = vv[c];
                z[c].x = fmaf(a.x, nk, w.x);
                z[c].y = fmaf(a.y, nk, w.y);
                z[c].z = fmaf(a.z, nk, w.z);
                z[c].w = fmaf(a.w, nk, w.w);
                M0 = fmaxf(M0, fmaxf(z[c].x, z[c].y));
                M1 = fmaxf(M1, fmaxf(z[c].z, z[c].w));
            }
            const float M = fmaxf(M0, M1);
            float S0 = 0.f, S1 = 0.f, S2 = 0.f, S3 = 0.f;
            #pragma unroll
            for (int c = 0; c < NC4R; c++) if (c < nc4) {
                S0 += ex2f_(z[c].x - M);
                S1 += ex2f_(z[c].y - M);
                S2 += ex2f_(z[c].z - M);
                S3 += ex2f_(z[c].w - M);
            }
            const float lse = fmaf(c1, M + lg2f_((S0 + S1) + (S2 + S3)), c2);
            myv = 0.5f * (myv + lse);
        }
    }
    __syncthreads();   // protect V reuse as reduction scratch

    // div = (sum_f + sum_g - sum_px - sum_py)/n
    float val = act ? ((g < 2) ? myv : -myv) : 0.f;
    #pragma unroll
    for (int o = 16; o; o >>= 1) val += __shfl_xor_sync(0xffffffffu, val, o);
    if ((t & 31) == 0) V[t >> 5] = val;
    __syncthreads();
    if (t == 0) {
        float s = 0.f;
        const int nw = THREADS / 32;
        for (int w = 0; w < nw; w++) s += V[w];
        g_scratch[(first + pl) * BATCH + b] = s / (float)n;
    }
}

__global__ void reduce_kernel(float* __restrict__ out)
{
    __shared__ float red[32];
    float s = 0.f;
    for (int i = threadIdx.x; i < NPARTS * BATCH; i += 1024) s += g_scratch[i];
    #pragma unroll
    for (int o = 16; o; o >>= 1) s += __shfl_xor_sync(0xffffffffu, s, o);
    if ((threadIdx.x & 31) == 0) red[threadIdx.x >> 5] = s;
    __syncthreads();
    if (threadIdx.x < 32) {
        float v = red[threadIdx.x];
        #pragma unroll
        for (int o = 16; o; o >>= 1) v += __shfl_xor_sync(0xffffffffu, v, o);
        if (threadIdx.x == 0) out[0] = v * (1.0f / (float)BATCH);
    }
}

extern "C" void kernel_launch(void* const* d_in, const int* in_sizes, int n_in,
                              void* d_out, int out_size)
{
    const float* pred = (const float*)d_in[0];
    const float* pc   = (const float*)d_in[1];

    // smem = (4n + 16) * ld * 4 bytes (max ld per class)
    const int smem1 = (4*45 + 16) * 52 * 4;   // 40,768  x4 CTAs (reg-lim)
    const int smem2 = (4*35 + 16) * 36 * 4;   // 22,464  x6 CTAs
    const int smem3 = (4*64 + 16) * 68 * 4;   // 73,984  x2 CTAs
    const int smem4 = (4*60 + 16) * 60 * 4;   // 61,440  x2 CTAs
    const int smem5 = (4*92 + 16) * 92 * 4;   // 141,312 x1 CTA

    cudaFuncSetAttribute((const void*)sinkhorn_kernel<45,13,192,4>, cudaFuncAttributeMaxDynamicSharedMemorySize, smem1);
    cudaFuncSetAttribute((const void*)sinkhorn_kernel<35, 9,160,6>, cudaFuncAttributeMaxDynamicSharedMemorySize, smem2);
    cudaFuncSetAttribute((const void*)sinkhorn_kernel<64,17,256,2>, cudaFuncAttributeMaxDynamicSharedMemorySize, smem3);
    cudaFuncSetAttribute((const void*)sinkhorn_kernel<60,15,256,2>, cudaFuncAttributeMaxDynamicSharedMemorySize, smem4);
    cudaFuncSetAttribute((const void*)sinkhorn_kernel<92,23,384,1>, cudaFuncAttributeMaxDynamicSharedMemorySize, smem5);

    sinkhorn_kernel<45,13,192,4><<<9 * BATCH, 192, smem1>>>(pred, pc,  0);
    sinkhorn_kernel<35, 9,160,6><<<3 * BATCH, 160, smem2>>>(pred, pc,  9);
    sinkhorn_kernel<64,17,256,2><<<4 * BATCH, 256, smem3>>>(pred, pc, 12);
    sinkhorn_kernel<60,15,256,2><<<3 * BATCH, 256, smem4>>>(pred, pc, 16);
    sinkhorn_kernel<92,23,384,1><<<1 * BATCH, 384, smem5>>>(pred, pc, 19);
    reduce_kernel<<<1, 1024>>>((float*)d_out);
}